// round 13
// baseline (speedup 1.0000x reference)
#include <cuda_runtime.h>
#include <cub/cub.cuh>
#include <math.h>
#include <math_constants.h>

#define HD 200
#define NMAX 50000
#define EMAX 800000
#define TOTMAX (NMAX + EMAX)
#define OUTLEN 512
#define TAILN 2048   // 1024 threads * 2 items
#define MT 180       // GEMM M-tile
#define NCHUNK 4     // pipeline chunks for k_gat -> next GEMM overlap

// ---------------- static device scratch ----------------
__device__ float g_bufA[(size_t)NMAX * HD];
__device__ float g_bufB[(size_t)NMAX * HD];
__device__ float g_hW[(size_t)NMAX * HD];
__device__ float g_hW2[(size_t)NMAX * HD];
__device__ float g_asA[NMAX];
__device__ float g_adA[NMAX];
__device__ float g_asB[NMAX];
__device__ float g_adB[NMAX];
__device__ float g_ew[TOTMAX];
__device__ int   g_deg[NMAX + 1];
__device__ int   g_indptr[NMAX + 1];
__device__ unsigned g_skey_in[TOTMAX];
__device__ unsigned g_skey_out[TOTMAX];
__device__ unsigned g_sval_in[TOTMAX];
__device__ unsigned g_csr[TOTMAX];          // sorted-by-dst adjacency (bit31 = self loop)
__device__ float g_score[NMAX];
__device__ float g_svals[NMAX];
__device__ int   g_iota[NMAX];
__device__ int   g_perm[NMAX];
__device__ float g_yA[NMAX], g_yB[NMAX];
__device__ float g_rA[NMAX], g_rB[NMAX];
__device__ float g_cA[NMAX], g_cB[NMAX];
__device__ int   g_origA[NMAX];
__device__ int   g_origB[NMAX];
__device__ int   g_curof[NMAX];             // stamp<<16 | current index
__device__ unsigned char g_tmp[64u << 20];  // cub temp storage

// ---------------- threefry2x32 (exact JAX PRNG) ----------------
__host__ __device__ __forceinline__ void tf2x32(unsigned k0, unsigned k1,
                                                unsigned x0, unsigned x1,
                                                unsigned& o0, unsigned& o1) {
  unsigned ks2 = k0 ^ k1 ^ 0x1BD11BDAu;
  x0 += k0; x1 += k1;
#define TFR(r) { x0 += x1; x1 = (x1 << (r)) | (x1 >> (32 - (r))); x1 ^= x0; }
  TFR(13) TFR(15) TFR(26) TFR(6)   x0 += k1;  x1 += ks2 + 1u;
  TFR(17) TFR(29) TFR(16) TFR(24)  x0 += ks2; x1 += k0 + 2u;
  TFR(13) TFR(15) TFR(26) TFR(6)   x0 += k0;  x1 += k1 + 3u;
  TFR(17) TFR(29) TFR(16) TFR(24)  x0 += k1;  x1 += ks2 + 4u;
  TFR(13) TFR(15) TFR(26) TFR(6)   x0 += ks2; x1 += k0 + 5u;
#undef TFR
  o0 = x0; o1 = x1;
}

// XLA f32 tanh
__device__ __forceinline__ float xla_tanh(float x) {
  float ax = fabsf(x);
  float xc = fminf(fmaxf(x, -9.0f), 9.0f);
  float x2 = xc * xc;
  float p = -2.76076847742355e-16f;
  p = fmaf(x2, p, 2.00018790482477e-13f);
  p = fmaf(x2, p, -8.60467152213735e-11f);
  p = fmaf(x2, p, 5.12229709037114e-08f);
  p = fmaf(x2, p, 1.48572235717979e-05f);
  p = fmaf(x2, p, 6.37261928875436e-04f);
  p = fmaf(x2, p, 4.89352455891786e-03f);
  p = xc * p;
  float q = 1.19825839466702e-06f;
  q = fmaf(x2, q, 1.18534705686654e-04f);
  q = fmaf(x2, q, 2.26843463243900e-03f);
  q = fmaf(x2, q, 4.89352518554385e-03f);
  return ax < 0.0004f ? x : __fdiv_rn(p, q);
}

// ---------------- packed f32x2 helpers ----------------
__device__ __forceinline__ void ffma2(unsigned long long& d, unsigned long long a,
                                      unsigned long long b) {
  asm("fma.rn.f32x2 %0, %1, %2, %0;" : "+l"(d) : "l"(a), "l"(b));
}
__device__ __forceinline__ void unpack2(unsigned long long v, float& lo, float& hi) {
  asm("mov.b64 {%0, %1}, %2;" : "=f"(lo), "=f"(hi) : "l"(v));
}

// ---------------- CSR construction ----------------
__global__ void k_deginit(int N) {
  int t = blockIdx.x * blockDim.x + threadIdx.x;
  if (t <= N) g_deg[t] = (t < N) ? 1 : 0;
}
__global__ void k_edges(const int* __restrict__ src, const int* __restrict__ dst,
                        int N, int E) {
  int t = blockIdx.x * blockDim.x + threadIdx.x;
  if (t < E) {
    int d = dst[t];
    atomicAdd(&g_deg[d], 1);
    g_skey_in[t] = (unsigned)d;
    g_sval_in[t] = (unsigned)src[t];
  } else if (t < E + N) {
    int i = t - E;
    g_skey_in[t] = (unsigned)i;
    g_sval_in[t] = (unsigned)i | 0x80000000u;
  }
}

// ---- SGEMM + fused alpha: C=A@B; 180x200 tile, 360 thr; rows [mbase, ...) ----
__global__ __launch_bounds__(360, 1)
void k_sgemm(const float* __restrict__ A, const float* __restrict__ B,
             float* __restrict__ C, int M, int Nn, int K,
             const float* __restrict__ avec_s, const float* __restrict__ avec_d,
             float* __restrict__ as_out, float* __restrict__ ad_out,
             int doAlpha, int mbase) {
  __shared__ __align__(16) float As[2][8][MT];
  __shared__ __align__(16) float Bs[2][8][200];
  __shared__ __align__(16) float Bw[2][8][200];
  __shared__ float red[MT][20];
  int tid = threadIdx.x;
  int tx = tid % 20, ty = tid / 20;
  int m0 = mbase + blockIdx.x * MT, n0 = blockIdx.y * 200;

  int arow = tid >> 1, akq = (tid & 1) * 4;
  int bkk0 = tid / 50, bc40 = (tid % 50) * 4;
  int i1 = tid + 360;
  int bkk1 = i1 / 50, bc41 = (i1 % 50) * 4;
  bool bact1 = (tid < 40);

  unsigned long long accd[5][5], accx[5][5];
#pragma unroll
  for (int i = 0; i < 5; i++)
#pragma unroll
    for (int j = 0; j < 5; j++) { accd[i][j] = 0ull; accx[i][j] = 0ull; }

  int nsteps = K >> 3;

  auto fetchA = [&](int s) -> float4 {
    int gm = m0 + arow;
    if (gm < M) return *(const float4*)(A + (size_t)gm * K + s * 8 + akq);
    return make_float4(0.f, 0.f, 0.f, 0.f);
  };
  auto fetchBidx = [&](int s, int kk, int c4) -> float4 {
    int gn = n0 + c4;
    const float* row = B + (size_t)(s * 8 + kk) * Nn;
    if (gn + 3 < Nn) return *(const float4*)(row + gn);
    float4 v = make_float4(0.f, 0.f, 0.f, 0.f);
    if (gn + 0 < Nn) v.x = row[gn + 0];
    if (gn + 1 < Nn) v.y = row[gn + 1];
    if (gn + 2 < Nn) v.z = row[gn + 2];
    return v;
  };
  auto storeA = [&](float4 v, int buf) {
    As[buf][akq + 0][arow] = v.x;
    As[buf][akq + 1][arow] = v.y;
    As[buf][akq + 2][arow] = v.z;
    As[buf][akq + 3][arow] = v.w;
  };
  auto storeB = [&](float4 v0, float4 v1, int buf) {
    *(float4*)&Bs[buf][bkk0][bc40] = v0;
    *(float4*)&Bw[buf][bkk0][bc40] = make_float4(v0.y, v0.x, v0.w, v0.z);
    if (bact1) {
      *(float4*)&Bs[buf][bkk1][bc41] = v1;
      *(float4*)&Bw[buf][bkk1][bc41] = make_float4(v1.y, v1.x, v1.w, v1.z);
    }
  };

  {
    float4 ra = fetchA(0);
    float4 rb0 = fetchBidx(0, bkk0, bc40);
    float4 rb1 = bact1 ? fetchBidx(0, bkk1, bc41) : make_float4(0, 0, 0, 0);
    storeA(ra, 0);
    storeB(rb0, rb1, 0);
  }
  __syncthreads();

  int buf = 0;
  for (int s = 0; s < nsteps; s++) {
    float4 ra, rb0, rb1;
    bool pf = (s + 1 < nsteps);
    if (pf) {
      ra = fetchA(s + 1);
      rb0 = fetchBidx(s + 1, bkk0, bc40);
      rb1 = bact1 ? fetchBidx(s + 1, bkk1, bc41) : make_float4(0, 0, 0, 0);
    }
#pragma unroll
    for (int kk = 0; kk < 8; kk++) {
      const unsigned long long* ap =
          (const unsigned long long*)&As[buf][kk][ty * 10];
      const unsigned long long* bp =
          (const unsigned long long*)&Bs[buf][kk][tx * 10];
      const unsigned long long* wp =
          (const unsigned long long*)&Bw[buf][kk][tx * 10];
      unsigned long long a2[5], b2[5], w2[5];
#pragma unroll
      for (int q = 0; q < 5; q++) { a2[q] = ap[q]; b2[q] = bp[q]; w2[q] = wp[q]; }
#pragma unroll
      for (int i = 0; i < 5; i++)
#pragma unroll
        for (int j = 0; j < 5; j++) {
          ffma2(accd[i][j], a2[i], b2[j]);
          ffma2(accx[i][j], a2[i], w2[j]);
        }
    }
    if (pf) {
      storeA(ra, buf ^ 1);
      storeB(rb0, rb1, buf ^ 1);
      __syncthreads();
      buf ^= 1;
    }
  }

  float asv[10], adv[10];
  if (doAlpha) {
#pragma unroll
    for (int t = 0; t < 10; t++) {
      int gn = n0 + tx * 10 + t;
      asv[t] = (gn < Nn) ? avec_s[gn] : 0.f;
      adv[t] = (gn < Nn) ? avec_d[gn] : 0.f;
    }
  }
  float sp[10], dp[10];
#pragma unroll
  for (int t = 0; t < 10; t++) { sp[t] = 0.f; dp[t] = 0.f; }

#pragma unroll
  for (int i = 0; i < 5; i++) {
    int r0 = ty * 10 + 2 * i, r1 = r0 + 1;
    int gm0 = m0 + r0, gm1 = m0 + r1;
    float row0[10], row1[10];
#pragma unroll
    for (int j = 0; j < 5; j++) {
      float d0, d1, x0, x1;
      unpack2(accd[i][j], d0, d1);
      unpack2(accx[i][j], x0, x1);
      row0[2 * j] = d0; row0[2 * j + 1] = x0;
      row1[2 * j] = x1; row1[2 * j + 1] = d1;
    }
    if (gm0 < M) {
      float* Crow = C + (size_t)gm0 * Nn;
      int c0 = n0 + tx * 10;
#pragma unroll
      for (int j = 0; j < 5; j++)
        if (c0 + 2 * j + 1 < Nn)
          *(float2*)(Crow + c0 + 2 * j) = make_float2(row0[2 * j], row0[2 * j + 1]);
    }
    if (gm1 < M) {
      float* Crow = C + (size_t)gm1 * Nn;
      int c0 = n0 + tx * 10;
#pragma unroll
      for (int j = 0; j < 5; j++)
        if (c0 + 2 * j + 1 < Nn)
          *(float2*)(Crow + c0 + 2 * j) = make_float2(row1[2 * j], row1[2 * j + 1]);
    }
    if (doAlpha) {
#pragma unroll
      for (int t = 0; t < 10; t++) {
        sp[2 * i] = fmaf(row0[t], asv[t], sp[2 * i]);
        dp[2 * i] = fmaf(row0[t], adv[t], dp[2 * i]);
        sp[2 * i + 1] = fmaf(row1[t], asv[t], sp[2 * i + 1]);
        dp[2 * i + 1] = fmaf(row1[t], adv[t], dp[2 * i + 1]);
      }
    }
  }

  if (doAlpha) {
    __syncthreads();
#pragma unroll
    for (int t = 0; t < 10; t++) red[ty * 10 + t][tx] = sp[t];
    __syncthreads();
    if (tid < MT) {
      int gm = m0 + tid;
      if (gm < M) {
        float s1 = 0.f;
#pragma unroll
        for (int t = 0; t < 20; t++) s1 += red[tid][t];
        as_out[gm] = s1;
      }
    }
    __syncthreads();
#pragma unroll
    for (int t = 0; t < 10; t++) red[ty * 10 + t][tx] = dp[t];
    __syncthreads();
    if (tid < MT) {
      int gm = m0 + tid;
      if (gm < M) {
        float s2 = 0.f;
#pragma unroll
        for (int t = 0; t < 20; t++) s2 += red[tid][t];
        ad_out[gm] = s2;
      }
    }
  }
}

// ---- GAT aggregation over node range [ns, ne) + dropout (+ y/r fusion) ----
__global__ __launch_bounds__(256)
void k_gat(const float* __restrict__ hW, const float* __restrict__ bias,
           const float* __restrict__ asv, const float* __restrict__ adv,
           float* __restrict__ out, int ns, int ne,
           unsigned fk0, unsigned fk1,
           const float* __restrict__ wrel, const float* __restrict__ wroot,
           float* __restrict__ yout, float* __restrict__ rout, int doYR) {
  int gw = ns + ((blockIdx.x * blockDim.x + threadIdx.x) >> 5);
  int lane = threadIdx.x & 31;
  if (gw >= ne) return;
  int beg = g_indptr[gw], end = g_indptr[gw + 1];
  int deg = end - beg;
  float adi = adv[gw];

  float acc[7];
#pragma unroll
  for (int q = 0; q < 7; q++) acc[q] = 0.f;

  if (deg <= 32) {
    int sreg = 0;
    float treg = 0.f;
    if (lane < deg) {
      sreg = (int)(g_csr[beg + lane] & 0x7fffffffu);
      float e = asv[sreg] + adi;
      e = e >= 0.f ? e : 0.2f * e;
      treg = expf(e);
    }
    float ssum = treg;
#pragma unroll
    for (int o = 16; o; o >>= 1) ssum += __shfl_xor_sync(0xffffffffu, ssum, o);
    float inv = 1.0f / ssum;

    int j = 0;
    for (; j + 3 < deg; j += 4) {
      int s0 = __shfl_sync(0xffffffffu, sreg, j + 0);
      int s1 = __shfl_sync(0xffffffffu, sreg, j + 1);
      int s2 = __shfl_sync(0xffffffffu, sreg, j + 2);
      int s3 = __shfl_sync(0xffffffffu, sreg, j + 3);
      float w0 = __shfl_sync(0xffffffffu, treg, j + 0) * inv;
      float w1 = __shfl_sync(0xffffffffu, treg, j + 1) * inv;
      float w2 = __shfl_sync(0xffffffffu, treg, j + 2) * inv;
      float w3 = __shfl_sync(0xffffffffu, treg, j + 3) * inv;
      const float* h0 = hW + (size_t)s0 * HD;
      const float* h1 = hW + (size_t)s1 * HD;
      const float* h2 = hW + (size_t)s2 * HD;
      const float* h3 = hW + (size_t)s3 * HD;
#pragma unroll
      for (int q = 0; q < 7; q++) {
        int c = lane + q * 32;
        if (c < HD) {
          float v0 = h0[c], v1 = h1[c], v2 = h2[c], v3 = h3[c];
          acc[q] = fmaf(w0, v0, fmaf(w1, v1, fmaf(w2, v2, fmaf(w3, v3, acc[q]))));
        }
      }
    }
    for (; j < deg; j++) {
      int s0 = __shfl_sync(0xffffffffu, sreg, j);
      float w0 = __shfl_sync(0xffffffffu, treg, j) * inv;
      const float* h0 = hW + (size_t)s0 * HD;
#pragma unroll
      for (int q = 0; q < 7; q++) {
        int c = lane + q * 32;
        if (c < HD) acc[q] = fmaf(w0, h0[c], acc[q]);
      }
    }
  } else {
    float ssum = 0.f;
    for (int j = beg + lane; j < end; j += 32) {
      int s = (int)(g_csr[j] & 0x7fffffffu);
      float e = asv[s] + adi;
      e = e >= 0.f ? e : 0.2f * e;
      float t = expf(e);
      g_ew[j] = t;
      ssum += t;
    }
#pragma unroll
    for (int o = 16; o; o >>= 1) ssum += __shfl_xor_sync(0xffffffffu, ssum, o);
    float inv = 1.0f / ssum;
    __threadfence_block();
    __syncwarp();
    int j = beg;
    for (; j + 1 < end; j += 2) {
      int s0 = (int)(g_csr[j] & 0x7fffffffu);
      int s1 = (int)(g_csr[j + 1] & 0x7fffffffu);
      float w0 = g_ew[j] * inv;
      float w1 = g_ew[j + 1] * inv;
      const float* h0 = hW + (size_t)s0 * HD;
      const float* h1 = hW + (size_t)s1 * HD;
#pragma unroll
      for (int q = 0; q < 7; q++) {
        int c = lane + q * 32;
        if (c < HD) acc[q] = fmaf(w0, h0[c], fmaf(w1, h1[c], acc[q]));
      }
    }
    if (j < end) {
      int s0 = (int)(g_csr[j] & 0x7fffffffu);
      float w0 = g_ew[j] * inv;
      const float* h0 = hW + (size_t)s0 * HD;
#pragma unroll
      for (int q = 0; q < 7; q++) {
        int c = lane + q * 32;
        if (c < HD) acc[q] = fmaf(w0, h0[c], acc[q]);
      }
    }
  }

  size_t base = (size_t)gw * HD;
  float yacc = 0.f, racc = 0.f;
#pragma unroll
  for (int q = 0; q < 7; q++) {
    int c = lane + q * 32;
    if (c >= HD) continue;
    float v = acc[q] + bias[c];
    v = v > 0.f ? v : 0.f;
    unsigned idx = (unsigned)gw * (unsigned)HD + (unsigned)c;
    unsigned o0, o1;
    tf2x32(fk0, fk1, 0u, idx, o0, o1);
    unsigned bbits = o0 ^ o1;
    float u = __uint_as_float((bbits >> 9) | 0x3f800000u) - 1.0f;
    v = (u < 0.8f) ? __fdiv_rn(v, 0.8f) : 0.f;
    out[base + c] = v;
    if (doYR) {
      yacc = fmaf(v, wrel[c], yacc);
      racc = fmaf(v, wroot[c], racc);
    }
  }
  if (doYR) {
#pragma unroll
    for (int o = 16; o; o >>= 1) {
      yacc += __shfl_xor_sync(0xffffffffu, yacc, o);
      racc += __shfl_xor_sync(0xffffffffu, racc, o);
    }
    if (!lane) {
      yout[gw] = yacc; rout[gw] = racc;
      g_origA[gw] = gw; g_curof[gw] = gw; g_cA[gw] = 1.0f;
    }
  }
}

// ---------------- pooling (scalar recurrence) ----------------
__global__ void k_score(const int* __restrict__ orig, const float* __restrict__ ycur,
                        const float* __restrict__ rcur,
                        const float* __restrict__ bpool, int n, int iter) {
  int gw = (blockIdx.x * blockDim.x + threadIdx.x) >> 5;
  int lane = threadIdx.x & 31;
  if (gw >= n) return;
  int o = orig[gw];
  int beg = g_indptr[o], end = g_indptr[o + 1];
  float acc = 0.f;
  for (int j = beg + lane; j < end; j += 32) {
    unsigned v = g_csr[j];
    if (v & 0x80000000u) continue;
    int cv = g_curof[v];
    if ((cv >> 16) == iter) acc += ycur[cv & 0xffff];
  }
#pragma unroll
  for (int off = 16; off; off >>= 1) acc += __shfl_xor_sync(0xffffffffu, acc, off);
  if (!lane) {
    g_score[gw] = xla_tanh(acc + rcur[gw] + bpool[0]);
    g_iota[gw] = gw;
  }
}
__global__ void k_update(const int* __restrict__ oin, int* __restrict__ oout,
                         const float* __restrict__ yin, float* __restrict__ yout,
                         const float* __restrict__ rin, float* __restrict__ rout,
                         const float* __restrict__ cin, float* __restrict__ cout,
                         int k, int stampNext) {
  int i = blockIdx.x * blockDim.x + threadIdx.x;
  if (i >= k) return;
  int p = g_perm[i];
  float val = g_svals[i];
  yout[i] = yin[p] * val;
  rout[i] = rin[p] * val;
  cout[i] = cin[p] * val;
  int o = oin[p];
  oout[i] = o;
  g_curof[o] = stampNext | i;
}
__global__ __launch_bounds__(1024)
void k_sortupd(const int* __restrict__ oin, int* __restrict__ oout,
               const float* __restrict__ yin, float* __restrict__ yout,
               const float* __restrict__ rin, float* __restrict__ rout,
               const float* __restrict__ cin, float* __restrict__ cout,
               int n, int k, int stampNext, int finalize,
               const float* __restrict__ h3, float* __restrict__ out) {
  using BRS = cub::BlockRadixSort<float, 1024, 2, int>;
  __shared__ typename BRS::TempStorage ts;
  float keys[2];
  int vals[2];
#pragma unroll
  for (int q = 0; q < 2; q++) {
    int i = threadIdx.x * 2 + q;
    keys[q] = (i < n) ? g_score[i] : -CUDART_INF_F;
    vals[q] = i;
  }
  BRS(ts).SortDescending(keys, vals);
#pragma unroll
  for (int q = 0; q < 2; q++) {
    int p = threadIdx.x * 2 + q;
    if (p < k) {
      int v = vals[q];
      float val = keys[q];
      yout[p] = yin[v] * val;
      rout[p] = rin[v] * val;
      cout[p] = cin[v] * val;
      int o = oin[v];
      oout[p] = o;
      g_curof[o] = stampNext | p;
    }
  }
  if (finalize) {
    __syncthreads();
    for (int t = threadIdx.x; t < OUTLEN * HD; t += 1024) {
      int row = t / HD, c = t - row * HD;
      out[t] = (row < k) ? h3[(size_t)oout[row] * HD + c] * cout[row] : 0.f;
    }
  }
}
__global__ void k_final(const float* __restrict__ h3, const int* __restrict__ orig,
                        const float* __restrict__ cum, int n,
                        float* __restrict__ out) {
  int t = blockIdx.x * blockDim.x + threadIdx.x;
  if (t >= OUTLEN * HD) return;
  int row = t / HD, c = t - row * HD;
  out[t] = (row < n) ? h3[(size_t)orig[row] * HD + c] * cum[row] : 0.f;
}

// ---------------- host driver ----------------
extern "C" void kernel_launch(void* const* d_in, const int* in_sizes, int n_in,
                              void* d_out, int out_size) {
  const float* x     = (const float*)d_in[0];
  const int*   src   = (const int*)d_in[1];
  const int*   dst   = (const int*)d_in[2];
  const float* W[3]  = {(const float*)d_in[3], (const float*)d_in[7], (const float*)d_in[11]};
  const float* Asv[3]= {(const float*)d_in[4], (const float*)d_in[8], (const float*)d_in[12]};
  const float* Adv[3]= {(const float*)d_in[5], (const float*)d_in[9], (const float*)d_in[13]};
  const float* Bv[3] = {(const float*)d_in[6], (const float*)d_in[10], (const float*)d_in[14]};
  const float* Wrel  = (const float*)d_in[15];
  const float* Wroot = (const float*)d_in[16];
  const float* bpool = (const float*)d_in[17];

  int H  = in_sizes[4];          // 200
  int ID = in_sizes[3] / H;      // 128
  int N  = in_sizes[0] / ID;     // 50000
  int E  = in_sizes[1];          // 800000
  if (N > NMAX || E > EMAX || H != HD) return;

  float *bufA, *bufB, *hWa, *hWb, *asA, *adA, *asB, *adB;
  int *deg, *indptr, *iota, *perm, *origA, *origB;
  float *score, *svals, *yA, *yB, *rA, *rB, *cA, *cB;
  unsigned *skin, *skout, *svin, *csr;
  unsigned char* tmp;
  cudaGetSymbolAddress((void**)&bufA, g_bufA);
  cudaGetSymbolAddress((void**)&bufB, g_bufB);
  cudaGetSymbolAddress((void**)&hWa, g_hW);
  cudaGetSymbolAddress((void**)&hWb, g_hW2);
  cudaGetSymbolAddress((void**)&asA, g_asA);
  cudaGetSymbolAddress((void**)&adA, g_adA);
  cudaGetSymbolAddress((void**)&asB, g_asB);
  cudaGetSymbolAddress((void**)&adB, g_adB);
  cudaGetSymbolAddress((void**)&deg, g_deg);
  cudaGetSymbolAddress((void**)&indptr, g_indptr);
  cudaGetSymbolAddress((void**)&skin, g_skey_in);
  cudaGetSymbolAddress((void**)&skout, g_skey_out);
  cudaGetSymbolAddress((void**)&svin, g_sval_in);
  cudaGetSymbolAddress((void**)&csr, g_csr);
  cudaGetSymbolAddress((void**)&score, g_score);
  cudaGetSymbolAddress((void**)&svals, g_svals);
  cudaGetSymbolAddress((void**)&iota, g_iota);
  cudaGetSymbolAddress((void**)&perm, g_perm);
  cudaGetSymbolAddress((void**)&origA, g_origA);
  cudaGetSymbolAddress((void**)&origB, g_origB);
  cudaGetSymbolAddress((void**)&yA, g_yA);
  cudaGetSymbolAddress((void**)&yB, g_yB);
  cudaGetSymbolAddress((void**)&rA, g_rA);
  cudaGetSymbolAddress((void**)&rB, g_rB);
  cudaGetSymbolAddress((void**)&cA, g_cA);
  cudaGetSymbolAddress((void**)&cB, g_cB);
  cudaGetSymbolAddress((void**)&tmp, g_tmp);

  cudaStream_t s2;
  cudaStreamCreateWithFlags(&s2, cudaStreamNonBlocking);
  cudaEvent_t evFork, evJoin, evG2, evG3;
  cudaEvent_t evA[NCHUNK], evB[NCHUNK];
  cudaEventCreateWithFlags(&evFork, cudaEventDisableTiming);
  cudaEventCreateWithFlags(&evJoin, cudaEventDisableTiming);
  cudaEventCreateWithFlags(&evG2, cudaEventDisableTiming);
  cudaEventCreateWithFlags(&evG3, cudaEventDisableTiming);
  for (int p = 0; p < NCHUNK; p++) {
    cudaEventCreateWithFlags(&evA[p], cudaEventDisableTiming);
    cudaEventCreateWithFlags(&evB[p], cudaEventDisableTiming);
  }

  int tilesTotal = (N + MT - 1) / MT;                 // 278
  int tilesPer = (tilesTotal + NCHUNK - 1) / NCHUNK;
  int chTiles[NCHUNK], chN0[NCHUNK], chN1[NCHUNK];
  for (int p = 0; p < NCHUNK; p++) {
    int t0 = p * tilesPer;
    int t1 = (t0 + tilesPer < tilesTotal) ? t0 + tilesPer : tilesTotal;
    chTiles[p] = (t1 > t0) ? (t1 - t0) : 0;
    chN0[p] = t0 * MT;
    int n1 = t1 * MT;
    chN1[p] = (n1 < N) ? n1 : N;
  }

  // ---- fork: layer-1 GEMM (+alphaA) -> hWa on s2, CSR build on main ----
  cudaEventRecord(evFork, (cudaStream_t)0);
  cudaStreamWaitEvent(s2, evFork, 0);
  k_sgemm<<<dim3(tilesTotal, 1), 360, 0, s2>>>(x, W[0], hWa, N, H, ID,
                                               Asv[0], Adv[0], asA, adA, 1, 0);
  cudaEventRecord(evJoin, s2);

  k_deginit<<<(N + 256) / 256, 256>>>(N);
  k_edges<<<(E + N + 255) / 256, 256>>>(src, dst, N, E);
  size_t tb = sizeof(g_tmp);
  cub::DeviceScan::ExclusiveSum(tmp, tb, deg, indptr, N + 1, (cudaStream_t)0);
  int bits = 1; while ((1 << bits) < N) bits++;
  tb = sizeof(g_tmp);
  cub::DeviceRadixSort::SortPairs(tmp, tb, skin, skout, svin, csr, N + E, 0, bits,
                                  (cudaStream_t)0);

  cudaStreamWaitEvent((cudaStream_t)0, evJoin, 0);

  unsigned fk[3][2];
  for (int l = 0; l < 3; l++) tf2x32(0u, 42u, 0u, (unsigned)l, fk[l][0], fk[l][1]);

  // ---- layer 1: k_gat reads hWa/alphaA -> bufA; GEMM2 -> hWb/alphaB ----
  for (int p = 0; p < NCHUNK; p++) {
    int cnt = chN1[p] - chN0[p];
    if (cnt <= 0) continue;
    k_gat<<<(cnt * 32 + 255) / 256, 256>>>(hWa, Bv[0], asA, adA, bufA,
                                           chN0[p], chN1[p],
                                           fk[0][0], fk[0][1],
                                           Wrel, Wroot, yA, rA, 0);
    cudaEventRecord(evA[p], (cudaStream_t)0);
    cudaStreamWaitEvent(s2, evA[p], 0);
    if (chTiles[p] > 0)
      k_sgemm<<<dim3(chTiles[p], 1), 360, 0, s2>>>(bufA, W[1], hWb, N, H, HD,
                                                   Asv[1], Adv[1], asB, adB,
                                                   1, chN0[p]);
  }
  cudaEventRecord(evG2, s2);
  cudaStreamWaitEvent((cudaStream_t)0, evG2, 0);

  // ---- layer 2: k_gat reads hWb/alphaB -> bufB; GEMM3 -> hWa/alphaA ----
  for (int p = 0; p < NCHUNK; p++) {
    int cnt = chN1[p] - chN0[p];
    if (cnt <= 0) continue;
    k_gat<<<(cnt * 32 + 255) / 256, 256>>>(hWb, Bv[1], asB, adB, bufB,
                                           chN0[p], chN1[p],
                                           fk[1][0], fk[1][1],
                                           Wrel, Wroot, yA, rA, 0);
    cudaEventRecord(evB[p], (cudaStream_t)0);
    cudaStreamWaitEvent(s2, evB[p], 0);
    if (chTiles[p] > 0)
      k_sgemm<<<dim3(chTiles[p], 1), 360, 0, s2>>>(bufB, W[2], hWa, N, H, HD,
                                                   Asv[2], Adv[2], asA, adA,
                                                   1, chN0[p]);
  }
  cudaEventRecord(evG3, s2);
  cudaStreamWaitEvent((cudaStream_t)0, evG3, 0);

  // ---- layer 3: k_gat reads hWa/alphaA -> bufA (y/r fusion + pooling init) ----
  k_gat<<<(N * 32 + 255) / 256, 256>>>(hWa, Bv[2], asA, adA, bufA, 0, N,
                                       fk[2][0], fk[2][1],
                                       Wrel, Wroot, yA, rA, 1);
  float* h3 = bufA;

  // ---- SAGPooling loop (scalar recurrence) ----
  int* orig = origA;  int* orig2 = origB;
  float *y = yA, *y2 = yB, *r = rA, *r2 = rB, *cu = cA, *cu2 = cB;
  int n = N;
  int iter = 0;
  bool finalized = false;
  for (;;) {
    int k = (n + 1) / 2;
    k_score<<<(n + 7) / 8, 256>>>(orig, y, r, bpool, n, iter);
    bool fin = (k <= OUTLEN);
    if (n <= TAILN) {
      k_sortupd<<<1, 1024>>>(orig, orig2, y, y2, r, r2, cu, cu2, n, k,
                             (iter + 1) << 16, fin ? 1 : 0, h3, (float*)d_out);
      if (fin) finalized = true;
    } else {
      tb = sizeof(g_tmp);
      cub::DeviceRadixSort::SortPairsDescending(tmp, tb, score, svals, iota, perm,
                                                n, 0, 32, (cudaStream_t)0);
      k_update<<<(k + 255) / 256, 256>>>(orig, orig2, y, y2, r, r2, cu, cu2, k,
                                         (iter + 1) << 16);
    }
    { int* t = orig; orig = orig2; orig2 = t; }
    { float* t = y; y = y2; y2 = t; }
    { float* t = r; r = r2; r2 = t; }
    { float* t = cu; cu = cu2; cu2 = t; }
    n = k;
    iter++;
    if (n <= OUTLEN) break;
  }
  if (!finalized)
    k_final<<<(OUTLEN * HD + 255) / 256, 256>>>(h3, orig, cu, n, (float*)d_out);

  cudaEventDestroy(evFork);
  cudaEventDestroy(evJoin);
  cudaEventDestroy(evG2);
  cudaEventDestroy(evG3);
  for (int p = 0; p < NCHUNK; p++) {
    cudaEventDestroy(evA[p]);
    cudaEventDestroy(evB[p]);
  }
  cudaStreamDestroy(s2);
}

// round 14
// speedup vs baseline: 1.1899x; 1.1899x over previous
#include <cuda_runtime.h>
#include <cub/cub.cuh>
#include <math.h>
#include <math_constants.h>

#define HD 200
#define NMAX 50000
#define EMAX 800000
#define TOTMAX (NMAX + EMAX)
#define OUTLEN 512
#define TAILN 2048   // 1024 threads * 2 items
#define MT 180       // GEMM M-tile

// ---------------- static device scratch ----------------
__device__ float g_bufA[(size_t)NMAX * HD];
__device__ float g_bufB[(size_t)NMAX * HD];
__device__ float g_hW[(size_t)NMAX * HD];
__device__ float g_asA[NMAX];
__device__ float g_adA[NMAX];
__device__ float g_ew[TOTMAX];
__device__ int   g_deg[NMAX + 1];
__device__ int   g_indptr[NMAX + 1];
__device__ unsigned g_skey_in[TOTMAX];
__device__ unsigned g_skey_out[TOTMAX];
__device__ unsigned g_sval_in[TOTMAX];
__device__ unsigned g_csr[TOTMAX];          // sorted-by-dst adjacency (bit31 = self loop)
__device__ float g_score[NMAX];
__device__ float g_svals[NMAX];
__device__ int   g_iota[NMAX];
__device__ int   g_perm[NMAX];
__device__ float g_yA[NMAX], g_yB[NMAX];
__device__ float g_rA[NMAX], g_rB[NMAX];
__device__ float g_cA[NMAX], g_cB[NMAX];
__device__ int   g_origA[NMAX];
__device__ int   g_origB[NMAX];
__device__ int   g_curof[NMAX];             // stamp<<16 | current index
__device__ unsigned char g_tmp[64u << 20];  // cub temp storage

// ---------------- threefry2x32 (exact JAX PRNG) ----------------
__host__ __device__ __forceinline__ void tf2x32(unsigned k0, unsigned k1,
                                                unsigned x0, unsigned x1,
                                                unsigned& o0, unsigned& o1) {
  unsigned ks2 = k0 ^ k1 ^ 0x1BD11BDAu;
  x0 += k0; x1 += k1;
#define TFR(r) { x0 += x1; x1 = (x1 << (r)) | (x1 >> (32 - (r))); x1 ^= x0; }
  TFR(13) TFR(15) TFR(26) TFR(6)   x0 += k1;  x1 += ks2 + 1u;
  TFR(17) TFR(29) TFR(16) TFR(24)  x0 += ks2; x1 += k0 + 2u;
  TFR(13) TFR(15) TFR(26) TFR(6)   x0 += k0;  x1 += k1 + 3u;
  TFR(17) TFR(29) TFR(16) TFR(24)  x0 += k1;  x1 += ks2 + 4u;
  TFR(13) TFR(15) TFR(26) TFR(6)   x0 += ks2; x1 += k0 + 5u;
#undef TFR
  o0 = x0; o1 = x1;
}

// XLA f32 tanh
__device__ __forceinline__ float xla_tanh(float x) {
  float ax = fabsf(x);
  float xc = fminf(fmaxf(x, -9.0f), 9.0f);
  float x2 = xc * xc;
  float p = -2.76076847742355e-16f;
  p = fmaf(x2, p, 2.00018790482477e-13f);
  p = fmaf(x2, p, -8.60467152213735e-11f);
  p = fmaf(x2, p, 5.12229709037114e-08f);
  p = fmaf(x2, p, 1.48572235717979e-05f);
  p = fmaf(x2, p, 6.37261928875436e-04f);
  p = fmaf(x2, p, 4.89352455891786e-03f);
  p = xc * p;
  float q = 1.19825839466702e-06f;
  q = fmaf(x2, q, 1.18534705686654e-04f);
  q = fmaf(x2, q, 2.26843463243900e-03f);
  q = fmaf(x2, q, 4.89352518554385e-03f);
  return ax < 0.0004f ? x : __fdiv_rn(p, q);
}

// ---------------- packed f32x2 helpers ----------------
__device__ __forceinline__ void ffma2(unsigned long long& d, unsigned long long a,
                                      unsigned long long b) {
  asm("fma.rn.f32x2 %0, %1, %2, %0;" : "+l"(d) : "l"(a), "l"(b));
}
__device__ __forceinline__ void unpack2(unsigned long long v, float& lo, float& hi) {
  asm("mov.b64 {%0, %1}, %2;" : "=f"(lo), "=f"(hi) : "l"(v));
}

// ---------------- CSR construction ----------------
__global__ void k_deginit(int N) {
  int t = blockIdx.x * blockDim.x + threadIdx.x;
  if (t <= N) g_deg[t] = (t < N) ? 1 : 0;
}
__global__ void k_edges(const int* __restrict__ src, const int* __restrict__ dst,
                        int N, int E) {
  int t = blockIdx.x * blockDim.x + threadIdx.x;
  if (t < E) {
    int d = dst[t];
    atomicAdd(&g_deg[d], 1);
    g_skey_in[t] = (unsigned)d;
    g_sval_in[t] = (unsigned)src[t];
  } else if (t < E + N) {
    int i = t - E;
    g_skey_in[t] = (unsigned)i;
    g_sval_in[t] = (unsigned)i | 0x80000000u;
  }
}

// ---- SGEMM + fused alpha: C=A@B; 180x200 tile, 360 thr ----
__global__ __launch_bounds__(360, 1)
void k_sgemm(const float* __restrict__ A, const float* __restrict__ B,
             float* __restrict__ C, int M, int Nn, int K,
             const float* __restrict__ avec_s, const float* __restrict__ avec_d,
             float* __restrict__ as_out, float* __restrict__ ad_out,
             int doAlpha, int mbase) {
  __shared__ __align__(16) float As[2][8][MT];
  __shared__ __align__(16) float Bs[2][8][200];
  __shared__ __align__(16) float Bw[2][8][200];
  __shared__ float red[MT][20];
  int tid = threadIdx.x;
  int tx = tid % 20, ty = tid / 20;
  int m0 = mbase + blockIdx.x * MT, n0 = blockIdx.y * 200;

  int arow = tid >> 1, akq = (tid & 1) * 4;
  int bkk0 = tid / 50, bc40 = (tid % 50) * 4;
  int i1 = tid + 360;
  int bkk1 = i1 / 50, bc41 = (i1 % 50) * 4;
  bool bact1 = (tid < 40);

  unsigned long long accd[5][5], accx[5][5];
#pragma unroll
  for (int i = 0; i < 5; i++)
#pragma unroll
    for (int j = 0; j < 5; j++) { accd[i][j] = 0ull; accx[i][j] = 0ull; }

  int nsteps = K >> 3;

  auto fetchA = [&](int s) -> float4 {
    int gm = m0 + arow;
    if (gm < M) return *(const float4*)(A + (size_t)gm * K + s * 8 + akq);
    return make_float4(0.f, 0.f, 0.f, 0.f);
  };
  auto fetchBidx = [&](int s, int kk, int c4) -> float4 {
    int gn = n0 + c4;
    const float* row = B + (size_t)(s * 8 + kk) * Nn;
    if (gn + 3 < Nn) return *(const float4*)(row + gn);
    float4 v = make_float4(0.f, 0.f, 0.f, 0.f);
    if (gn + 0 < Nn) v.x = row[gn + 0];
    if (gn + 1 < Nn) v.y = row[gn + 1];
    if (gn + 2 < Nn) v.z = row[gn + 2];
    return v;
  };
  auto storeA = [&](float4 v, int buf) {
    As[buf][akq + 0][arow] = v.x;
    As[buf][akq + 1][arow] = v.y;
    As[buf][akq + 2][arow] = v.z;
    As[buf][akq + 3][arow] = v.w;
  };
  auto storeB = [&](float4 v0, float4 v1, int buf) {
    *(float4*)&Bs[buf][bkk0][bc40] = v0;
    *(float4*)&Bw[buf][bkk0][bc40] = make_float4(v0.y, v0.x, v0.w, v0.z);
    if (bact1) {
      *(float4*)&Bs[buf][bkk1][bc41] = v1;
      *(float4*)&Bw[buf][bkk1][bc41] = make_float4(v1.y, v1.x, v1.w, v1.z);
    }
  };

  {
    float4 ra = fetchA(0);
    float4 rb0 = fetchBidx(0, bkk0, bc40);
    float4 rb1 = bact1 ? fetchBidx(0, bkk1, bc41) : make_float4(0, 0, 0, 0);
    storeA(ra, 0);
    storeB(rb0, rb1, 0);
  }
  __syncthreads();

  int buf = 0;
  for (int s = 0; s < nsteps; s++) {
    float4 ra, rb0, rb1;
    bool pf = (s + 1 < nsteps);
    if (pf) {
      ra = fetchA(s + 1);
      rb0 = fetchBidx(s + 1, bkk0, bc40);
      rb1 = bact1 ? fetchBidx(s + 1, bkk1, bc41) : make_float4(0, 0, 0, 0);
    }
#pragma unroll
    for (int kk = 0; kk < 8; kk++) {
      const unsigned long long* ap =
          (const unsigned long long*)&As[buf][kk][ty * 10];
      const unsigned long long* bp =
          (const unsigned long long*)&Bs[buf][kk][tx * 10];
      const unsigned long long* wp =
          (const unsigned long long*)&Bw[buf][kk][tx * 10];
      unsigned long long a2[5], b2[5], w2[5];
#pragma unroll
      for (int q = 0; q < 5; q++) { a2[q] = ap[q]; b2[q] = bp[q]; w2[q] = wp[q]; }
#pragma unroll
      for (int i = 0; i < 5; i++)
#pragma unroll
        for (int j = 0; j < 5; j++) {
          ffma2(accd[i][j], a2[i], b2[j]);
          ffma2(accx[i][j], a2[i], w2[j]);
        }
    }
    if (pf) {
      storeA(ra, buf ^ 1);
      storeB(rb0, rb1, buf ^ 1);
      __syncthreads();
      buf ^= 1;
    }
  }

  float asv[10], adv[10];
  if (doAlpha) {
#pragma unroll
    for (int t = 0; t < 10; t++) {
      int gn = n0 + tx * 10 + t;
      asv[t] = (gn < Nn) ? avec_s[gn] : 0.f;
      adv[t] = (gn < Nn) ? avec_d[gn] : 0.f;
    }
  }
  float sp[10], dp[10];
#pragma unroll
  for (int t = 0; t < 10; t++) { sp[t] = 0.f; dp[t] = 0.f; }

#pragma unroll
  for (int i = 0; i < 5; i++) {
    int r0 = ty * 10 + 2 * i, r1 = r0 + 1;
    int gm0 = m0 + r0, gm1 = m0 + r1;
    float row0[10], row1[10];
#pragma unroll
    for (int j = 0; j < 5; j++) {
      float d0, d1, x0, x1;
      unpack2(accd[i][j], d0, d1);
      unpack2(accx[i][j], x0, x1);
      row0[2 * j] = d0; row0[2 * j + 1] = x0;
      row1[2 * j] = x1; row1[2 * j + 1] = d1;
    }
    if (gm0 < M) {
      float* Crow = C + (size_t)gm0 * Nn;
      int c0 = n0 + tx * 10;
#pragma unroll
      for (int j = 0; j < 5; j++)
        if (c0 + 2 * j + 1 < Nn)
          *(float2*)(Crow + c0 + 2 * j) = make_float2(row0[2 * j], row0[2 * j + 1]);
    }
    if (gm1 < M) {
      float* Crow = C + (size_t)gm1 * Nn;
      int c0 = n0 + tx * 10;
#pragma unroll
      for (int j = 0; j < 5; j++)
        if (c0 + 2 * j + 1 < Nn)
          *(float2*)(Crow + c0 + 2 * j) = make_float2(row1[2 * j], row1[2 * j + 1]);
    }
    if (doAlpha) {
#pragma unroll
      for (int t = 0; t < 10; t++) {
        sp[2 * i] = fmaf(row0[t], asv[t], sp[2 * i]);
        dp[2 * i] = fmaf(row0[t], adv[t], dp[2 * i]);
        sp[2 * i + 1] = fmaf(row1[t], asv[t], sp[2 * i + 1]);
        dp[2 * i + 1] = fmaf(row1[t], adv[t], dp[2 * i + 1]);
      }
    }
  }

  if (doAlpha) {
    __syncthreads();
#pragma unroll
    for (int t = 0; t < 10; t++) red[ty * 10 + t][tx] = sp[t];
    __syncthreads();
    if (tid < MT) {
      int gm = m0 + tid;
      if (gm < M) {
        float s1 = 0.f;
#pragma unroll
        for (int t = 0; t < 20; t++) s1 += red[tid][t];
        as_out[gm] = s1;
      }
    }
    __syncthreads();
#pragma unroll
    for (int t = 0; t < 10; t++) red[ty * 10 + t][tx] = dp[t];
    __syncthreads();
    if (tid < MT) {
      int gm = m0 + tid;
      if (gm < M) {
        float s2 = 0.f;
#pragma unroll
        for (int t = 0; t < 20; t++) s2 += red[tid][t];
        ad_out[gm] = s2;
      }
    }
  }
}

// ---- GAT aggregation + dropout (+ y/r fusion) ----
__global__ __launch_bounds__(256)
void k_gat(const float* __restrict__ hW, const float* __restrict__ bias,
           const float* __restrict__ asv, const float* __restrict__ adv,
           float* __restrict__ out, int n,
           unsigned fk0, unsigned fk1,
           const float* __restrict__ wrel, const float* __restrict__ wroot,
           float* __restrict__ yout, float* __restrict__ rout, int doYR) {
  int gw = (blockIdx.x * blockDim.x + threadIdx.x) >> 5;
  int lane = threadIdx.x & 31;
  if (gw >= n) return;
  int beg = g_indptr[gw], end = g_indptr[gw + 1];
  int deg = end - beg;
  float adi = adv[gw];

  float acc[7];
#pragma unroll
  for (int q = 0; q < 7; q++) acc[q] = 0.f;

  if (deg <= 32) {
    int sreg = 0;
    float treg = 0.f;
    if (lane < deg) {
      sreg = (int)(g_csr[beg + lane] & 0x7fffffffu);
      float e = asv[sreg] + adi;
      e = e >= 0.f ? e : 0.2f * e;
      treg = expf(e);
    }
    float ssum = treg;
#pragma unroll
    for (int o = 16; o; o >>= 1) ssum += __shfl_xor_sync(0xffffffffu, ssum, o);
    float inv = 1.0f / ssum;

    int j = 0;
    for (; j + 3 < deg; j += 4) {
      int s0 = __shfl_sync(0xffffffffu, sreg, j + 0);
      int s1 = __shfl_sync(0xffffffffu, sreg, j + 1);
      int s2 = __shfl_sync(0xffffffffu, sreg, j + 2);
      int s3 = __shfl_sync(0xffffffffu, sreg, j + 3);
      float w0 = __shfl_sync(0xffffffffu, treg, j + 0) * inv;
      float w1 = __shfl_sync(0xffffffffu, treg, j + 1) * inv;
      float w2 = __shfl_sync(0xffffffffu, treg, j + 2) * inv;
      float w3 = __shfl_sync(0xffffffffu, treg, j + 3) * inv;
      const float* h0 = hW + (size_t)s0 * HD;
      const float* h1 = hW + (size_t)s1 * HD;
      const float* h2 = hW + (size_t)s2 * HD;
      const float* h3 = hW + (size_t)s3 * HD;
#pragma unroll
      for (int q = 0; q < 7; q++) {
        int c = lane + q * 32;
        if (c < HD) {
          float v0 = h0[c], v1 = h1[c], v2 = h2[c], v3 = h3[c];
          acc[q] = fmaf(w0, v0, fmaf(w1, v1, fmaf(w2, v2, fmaf(w3, v3, acc[q]))));
        }
      }
    }
    for (; j < deg; j++) {
      int s0 = __shfl_sync(0xffffffffu, sreg, j);
      float w0 = __shfl_sync(0xffffffffu, treg, j) * inv;
      const float* h0 = hW + (size_t)s0 * HD;
#pragma unroll
      for (int q = 0; q < 7; q++) {
        int c = lane + q * 32;
        if (c < HD) acc[q] = fmaf(w0, h0[c], acc[q]);
      }
    }
  } else {
    float ssum = 0.f;
    for (int j = beg + lane; j < end; j += 32) {
      int s = (int)(g_csr[j] & 0x7fffffffu);
      float e = asv[s] + adi;
      e = e >= 0.f ? e : 0.2f * e;
      float t = expf(e);
      g_ew[j] = t;
      ssum += t;
    }
#pragma unroll
    for (int o = 16; o; o >>= 1) ssum += __shfl_xor_sync(0xffffffffu, ssum, o);
    float inv = 1.0f / ssum;
    __threadfence_block();
    __syncwarp();
    int j = beg;
    for (; j + 1 < end; j += 2) {
      int s0 = (int)(g_csr[j] & 0x7fffffffu);
      int s1 = (int)(g_csr[j + 1] & 0x7fffffffu);
      float w0 = g_ew[j] * inv;
      float w1 = g_ew[j + 1] * inv;
      const float* h0 = hW + (size_t)s0 * HD;
      const float* h1 = hW + (size_t)s1 * HD;
#pragma unroll
      for (int q = 0; q < 7; q++) {
        int c = lane + q * 32;
        if (c < HD) acc[q] = fmaf(w0, h0[c], fmaf(w1, h1[c], acc[q]));
      }
    }
    if (j < end) {
      int s0 = (int)(g_csr[j] & 0x7fffffffu);
      float w0 = g_ew[j] * inv;
      const float* h0 = hW + (size_t)s0 * HD;
#pragma unroll
      for (int q = 0; q < 7; q++) {
        int c = lane + q * 32;
        if (c < HD) acc[q] = fmaf(w0, h0[c], acc[q]);
      }
    }
  }

  size_t base = (size_t)gw * HD;
  float yacc = 0.f, racc = 0.f;
#pragma unroll
  for (int q = 0; q < 7; q++) {
    int c = lane + q * 32;
    if (c >= HD) continue;
    float v = acc[q] + bias[c];
    v = v > 0.f ? v : 0.f;
    unsigned idx = (unsigned)gw * (unsigned)HD + (unsigned)c;
    unsigned o0, o1;
    tf2x32(fk0, fk1, 0u, idx, o0, o1);
    unsigned bbits = o0 ^ o1;
    // integer-domain equivalent of: float u = bits_to_[1,2) - 1; u < 0.8f
    // 0.8f = 6710886.5 * 2^-23, u = (bbits>>9) * 2^-23 exactly
    v = ((bbits >> 9) < 6710887u) ? __fdiv_rn(v, 0.8f) : 0.f;
    out[base + c] = v;
    if (doYR) {
      yacc = fmaf(v, wrel[c], yacc);
      racc = fmaf(v, wroot[c], racc);
    }
  }
  if (doYR) {
#pragma unroll
    for (int o = 16; o; o >>= 1) {
      yacc += __shfl_xor_sync(0xffffffffu, yacc, o);
      racc += __shfl_xor_sync(0xffffffffu, racc, o);
    }
    if (!lane) {
      yout[gw] = yacc; rout[gw] = racc;
      g_origA[gw] = gw; g_curof[gw] = gw; g_cA[gw] = 1.0f;
    }
  }
}

// ---------------- pooling (scalar recurrence) ----------------
__global__ void k_score(const int* __restrict__ orig, const float* __restrict__ ycur,
                        const float* __restrict__ rcur,
                        const float* __restrict__ bpool, int n, int iter) {
  int gw = (blockIdx.x * blockDim.x + threadIdx.x) >> 5;
  int lane = threadIdx.x & 31;
  if (gw >= n) return;
  int o = orig[gw];
  int beg = g_indptr[o], end = g_indptr[o + 1];
  float acc = 0.f;
  for (int j = beg + lane; j < end; j += 32) {
    unsigned v = g_csr[j];
    if (v & 0x80000000u) continue;
    int cv = g_curof[v];
    if ((cv >> 16) == iter) acc += ycur[cv & 0xffff];
  }
#pragma unroll
  for (int off = 16; off; off >>= 1) acc += __shfl_xor_sync(0xffffffffu, acc, off);
  if (!lane) {
    g_score[gw] = xla_tanh(acc + rcur[gw] + bpool[0]);
    g_iota[gw] = gw;
  }
}
__global__ void k_update(const int* __restrict__ oin, int* __restrict__ oout,
                         const float* __restrict__ yin, float* __restrict__ yout,
                         const float* __restrict__ rin, float* __restrict__ rout,
                         const float* __restrict__ cin, float* __restrict__ cout,
                         int k, int stampNext) {
  int i = blockIdx.x * blockDim.x + threadIdx.x;
  if (i >= k) return;
  int p = g_perm[i];
  float val = g_svals[i];
  yout[i] = yin[p] * val;
  rout[i] = rin[p] * val;
  cout[i] = cin[p] * val;
  int o = oin[p];
  oout[i] = o;
  g_curof[o] = stampNext | i;
}
__global__ __launch_bounds__(1024)
void k_sortupd(const int* __restrict__ oin, int* __restrict__ oout,
               const float* __restrict__ yin, float* __restrict__ yout,
               const float* __restrict__ rin, float* __restrict__ rout,
               const float* __restrict__ cin, float* __restrict__ cout,
               int n, int k, int stampNext, int finalize,
               const float* __restrict__ h3, float* __restrict__ out) {
  using BRS = cub::BlockRadixSort<float, 1024, 2, int>;
  __shared__ typename BRS::TempStorage ts;
  float keys[2];
  int vals[2];
#pragma unroll
  for (int q = 0; q < 2; q++) {
    int i = threadIdx.x * 2 + q;
    keys[q] = (i < n) ? g_score[i] : -CUDART_INF_F;
    vals[q] = i;
  }
  BRS(ts).SortDescending(keys, vals);
#pragma unroll
  for (int q = 0; q < 2; q++) {
    int p = threadIdx.x * 2 + q;
    if (p < k) {
      int v = vals[q];
      float val = keys[q];
      yout[p] = yin[v] * val;
      rout[p] = rin[v] * val;
      cout[p] = cin[v] * val;
      int o = oin[v];
      oout[p] = o;
      g_curof[o] = stampNext | p;
    }
  }
  if (finalize) {
    __syncthreads();
    for (int t = threadIdx.x; t < OUTLEN * HD; t += 1024) {
      int row = t / HD, c = t - row * HD;
      out[t] = (row < k) ? h3[(size_t)oout[row] * HD + c] * cout[row] : 0.f;
    }
  }
}
__global__ void k_final(const float* __restrict__ h3, const int* __restrict__ orig,
                        const float* __restrict__ cum, int n,
                        float* __restrict__ out) {
  int t = blockIdx.x * blockDim.x + threadIdx.x;
  if (t >= OUTLEN * HD) return;
  int row = t / HD, c = t - row * HD;
  out[t] = (row < n) ? h3[(size_t)orig[row] * HD + c] * cum[row] : 0.f;
}

// ---------------- host driver ----------------
extern "C" void kernel_launch(void* const* d_in, const int* in_sizes, int n_in,
                              void* d_out, int out_size) {
  const float* x     = (const float*)d_in[0];
  const int*   src   = (const int*)d_in[1];
  const int*   dst   = (const int*)d_in[2];
  const float* W[3]  = {(const float*)d_in[3], (const float*)d_in[7], (const float*)d_in[11]};
  const float* Asv[3]= {(const float*)d_in[4], (const float*)d_in[8], (const float*)d_in[12]};
  const float* Adv[3]= {(const float*)d_in[5], (const float*)d_in[9], (const float*)d_in[13]};
  const float* Bv[3] = {(const float*)d_in[6], (const float*)d_in[10], (const float*)d_in[14]};
  const float* Wrel  = (const float*)d_in[15];
  const float* Wroot = (const float*)d_in[16];
  const float* bpool = (const float*)d_in[17];

  int H  = in_sizes[4];          // 200
  int ID = in_sizes[3] / H;      // 128
  int N  = in_sizes[0] / ID;     // 50000
  int E  = in_sizes[1];          // 800000
  if (N > NMAX || E > EMAX || H != HD) return;

  float *bufA, *bufB, *hWa, *asA, *adA;
  int *deg, *indptr, *iota, *perm, *origA, *origB;
  float *score, *svals, *yA, *yB, *rA, *rB, *cA, *cB;
  unsigned *skin, *skout, *svin, *csr;
  unsigned char* tmp;
  cudaGetSymbolAddress((void**)&bufA, g_bufA);
  cudaGetSymbolAddress((void**)&bufB, g_bufB);
  cudaGetSymbolAddress((void**)&hWa, g_hW);
  cudaGetSymbolAddress((void**)&asA, g_asA);
  cudaGetSymbolAddress((void**)&adA, g_adA);
  cudaGetSymbolAddress((void**)&deg, g_deg);
  cudaGetSymbolAddress((void**)&indptr, g_indptr);
  cudaGetSymbolAddress((void**)&skin, g_skey_in);
  cudaGetSymbolAddress((void**)&skout, g_skey_out);
  cudaGetSymbolAddress((void**)&svin, g_sval_in);
  cudaGetSymbolAddress((void**)&csr, g_csr);
  cudaGetSymbolAddress((void**)&score, g_score);
  cudaGetSymbolAddress((void**)&svals, g_svals);
  cudaGetSymbolAddress((void**)&iota, g_iota);
  cudaGetSymbolAddress((void**)&perm, g_perm);
  cudaGetSymbolAddress((void**)&origA, g_origA);
  cudaGetSymbolAddress((void**)&origB, g_origB);
  cudaGetSymbolAddress((void**)&yA, g_yA);
  cudaGetSymbolAddress((void**)&yB, g_yB);
  cudaGetSymbolAddress((void**)&rA, g_rA);
  cudaGetSymbolAddress((void**)&rB, g_rB);
  cudaGetSymbolAddress((void**)&cA, g_cA);
  cudaGetSymbolAddress((void**)&cB, g_cB);
  cudaGetSymbolAddress((void**)&tmp, g_tmp);

  cudaStream_t s2;
  cudaEvent_t evFork, evJoin;
  cudaStreamCreateWithFlags(&s2, cudaStreamNonBlocking);
  cudaEventCreateWithFlags(&evFork, cudaEventDisableTiming);
  cudaEventCreateWithFlags(&evJoin, cudaEventDisableTiming);

  int tilesTotal = (N + MT - 1) / MT;   // 278

  // ---- fork: layer-1 GEMM (+alpha) -> hWa on s2, CSR build on main ----
  cudaEventRecord(evFork, (cudaStream_t)0);
  cudaStreamWaitEvent(s2, evFork, 0);
  k_sgemm<<<dim3(tilesTotal, 1), 360, 0, s2>>>(x, W[0], hWa, N, H, ID,
                                               Asv[0], Adv[0], asA, adA, 1, 0);
  cudaEventRecord(evJoin, s2);

  k_deginit<<<(N + 256) / 256, 256>>>(N);
  k_edges<<<(E + N + 255) / 256, 256>>>(src, dst, N, E);
  size_t tb = sizeof(g_tmp);
  cub::DeviceScan::ExclusiveSum(tmp, tb, deg, indptr, N + 1, (cudaStream_t)0);
  int bits = 1; while ((1 << bits) < N) bits++;
  tb = sizeof(g_tmp);
  cub::DeviceRadixSort::SortPairs(tmp, tb, skin, skout, svin, csr, N + E, 0, bits,
                                  (cudaStream_t)0);

  cudaStreamWaitEvent((cudaStream_t)0, evJoin, 0);

  unsigned fk[3][2];
  for (int l = 0; l < 3; l++) tf2x32(0u, 42u, 0u, (unsigned)l, fk[l][0], fk[l][1]);

  // ---- 3 GAT layers (sequential — overlap regressed; L2 is shared) ----
  float* houts[3] = {bufA, bufB, bufA};
  for (int l = 0; l < 3; l++) {
    if (l > 0)
      k_sgemm<<<dim3(tilesTotal, 1), 360>>>(houts[l - 1], W[l], hWa, N, H, HD,
                                            Asv[l], Adv[l], asA, adA, 1, 0);
    int doYR = (l == 2) ? 1 : 0;
    k_gat<<<(N * 32 + 255) / 256, 256>>>(hWa, Bv[l], asA, adA, houts[l], N,
                                         fk[l][0], fk[l][1],
                                         Wrel, Wroot, yA, rA, doYR);
  }
  float* h3 = houts[2];   // bufA

  // ---- SAGPooling loop (scalar recurrence) ----
  int* orig = origA;  int* orig2 = origB;
  float *y = yA, *y2 = yB, *r = rA, *r2 = rB, *cu = cA, *cu2 = cB;
  int n = N;
  int iter = 0;
  bool finalized = false;
  for (;;) {
    int k = (n + 1) / 2;
    k_score<<<(n + 7) / 8, 256>>>(orig, y, r, bpool, n, iter);
    bool fin = (k <= OUTLEN);
    if (n <= TAILN) {
      k_sortupd<<<1, 1024>>>(orig, orig2, y, y2, r, r2, cu, cu2, n, k,
                             (iter + 1) << 16, fin ? 1 : 0, h3, (float*)d_out);
      if (fin) finalized = true;
    } else {
      tb = sizeof(g_tmp);
      cub::DeviceRadixSort::SortPairsDescending(tmp, tb, score, svals, iota, perm,
                                                n, 0, 32, (cudaStream_t)0);
      k_update<<<(k + 255) / 256, 256>>>(orig, orig2, y, y2, r, r2, cu, cu2, k,
                                         (iter + 1) << 16);
    }
    { int* t = orig; orig = orig2; orig2 = t; }
    { float* t = y; y = y2; y2 = t; }
    { float* t = r; r = r2; r2 = t; }
    { float* t = cu; cu = cu2; cu2 = t; }
    n = k;
    iter++;
    if (n <= OUTLEN) break;
  }
  if (!finalized)
    k_final<<<(OUTLEN * HD + 255) / 256, 256>>>(h3, orig, cu, n, (float*)d_out);

  cudaEventDestroy(evFork);
  cudaEventDestroy(evJoin);
  cudaStreamDestroy(s2);
}